// round 14
// baseline (speedup 1.0000x reference)
#include <cuda_runtime.h>
#include <math.h>
#include <float.h>
#include <stdint.h>

constexpr int NB = 128, NA = 2, NH = 128, NW = 128;
constexpr int PLANE = NH * NW;
constexpr float THRESH = 0.6f;
constexpr float OBJ_SCALE = 5.0f;
constexpr float LN_MARGIN = 0.55961579f;   // ln(1.75) > ln(5/3)+fastlog-err margin
constexpr float POS_MARGIN = 1.30f;        // > 1.2889 exact positional bound
constexpr int ROWS_PER_BLOCK = 32;
constexpr int ROWS_PER_STAGE = 8;
constexpr int NSTAGES = ROWS_PER_BLOCK / ROWS_PER_STAGE;    // 4
constexpr int NBLOCKS = NB * NA * (NH / ROWS_PER_BLOCK);    // 1024
constexpr long long TOTAL_CELLS = (long long)NB * NA * NH * NW;
constexpr int STAGE_FLOATS = ROWS_PER_STAGE * NW;           // 1024
constexpr unsigned STAGE_BYTES = STAGE_FLOATS * 4;          // 4096 (c only)

// Accumulators (zero at module load; reset by last block each run)
__device__ double g_conf2 = 0.0;
__device__ unsigned long long g_cnt = 0ull;   // corrections only (negative)
__device__ float  g_sel = 0.0f;
__device__ unsigned g_done = 0u;

__device__ __forceinline__ float sig_fast(float x) {
    return __fdividef(1.0f, 1.0f + __expf(-x));
}
__device__ __forceinline__ uint32_t s2u(const void* p) {
    uint32_t r;
    asm("{ .reg .u64 t; cvta.to.shared.u64 t, %1; cvt.u32.u64 %0, t; }"
        : "=r"(r) : "l"(p));
    return r;
}
__device__ __forceinline__ void mbar_init(uint32_t mb, uint32_t cnt) {
    asm volatile("mbarrier.init.shared.b64 [%0], %1;" :: "r"(mb), "r"(cnt) : "memory");
}
__device__ __forceinline__ void mbar_expect(uint32_t mb, uint32_t bytes) {
    asm volatile("mbarrier.arrive.expect_tx.shared.b64 _, [%0], %1;"
                 :: "r"(mb), "r"(bytes) : "memory");
}
__device__ __forceinline__ void mbar_wait(uint32_t mb, uint32_t parity) {
    asm volatile(
        "{\n\t.reg .pred P;\n\t"
        "WL_%=:\n\t"
        "mbarrier.try_wait.parity.acquire.cta.shared::cta.b64 P, [%0], %1, 0x989680;\n\t"
        "@P bra.uni WD_%=;\n\t"
        "bra.uni WL_%=;\n\t"
        "WD_%=:\n\t}"
        :: "r"(mb), "r"(parity) : "memory");
}
__device__ __forceinline__ void bulk_g2s(uint32_t sdst, const float* gsrc,
                                         uint32_t bytes, uint32_t mb) {
    asm volatile(
        "cp.async.bulk.shared::cta.global.mbarrier::complete_tx::bytes "
        "[%0], [%1], %2, [%3];"
        :: "r"(sdst), "l"(gsrc), "r"(bytes), "r"(mb) : "memory");
}

__global__ void __launch_bounds__(256) k_fused(const float* __restrict__ out,
                                               const float* __restrict__ tgt,
                                               const float* __restrict__ anc,
                                               float* __restrict__ res) {
    __shared__ __align__(128) float sbuf[NSTAGES][STAGE_FLOATS];   // 16 KB (c only)
    __shared__ unsigned long long mbar[NSTAGES];
    __shared__ double sh_c2[8];
    __shared__ int    sh_ct[8];
    __shared__ float  sh_sv[8];

    int tid = threadIdx.x;
    int blk = blockIdx.x;
    int seg  = blk & 3;           // 32-row segment
    int slab = blk >> 2;          // b*2 + a
    int a = slab & 1;
    int b = slab >> 1;
    int j0 = seg * ROWS_PER_BLOCK;

    const float* slabp = out + (size_t)(b * 10 + a * 5) * PLANE;

    if (tid == 0) {
        #pragma unroll
        for (int s = 0; s < NSTAGES; s++) mbar_init(s2u(&mbar[s]), 1);
    }
    __syncthreads();

    // issue ALL stages up-front (c plane only; each mbar used once per launch)
    if (tid == 0) {
        #pragma unroll
        for (int s = 0; s < NSTAGES; s++) {
            uint32_t mb = s2u(&mbar[s]);
            mbar_expect(mb, STAGE_BYTES);
            bulk_g2s(s2u(&sbuf[s][0]),
                     slabp + 4 * (size_t)PLANE + (j0 + s * ROWS_PER_STAGE) * NW,
                     STAGE_BYTES, mb);
        }
    }

    // ---- per-thread constants (overlap the bulk copies) ----
    float4 t = __ldg((const float4*)(tgt + b * 4));
    float gx = t.x * (float)NW, gy = t.y * (float)NH;
    float gw = t.z * (float)NW, gh = t.w * (float)NH;
    float a0w = __ldg(anc + 0), a0h = __ldg(anc + 1);
    float a1w = __ldg(anc + 2), a1h = __ldg(anc + 3);
    float aw = a ? a1w : a0w;
    float ah = a ? a1h : a0h;
    float ga = gw * gh;
    float cc = __logf(__fdividef(ga, aw * ah));

    int r  = tid >> 5;            // row within stage (0..7)
    int c4 = (tid & 31) * 4;      // 4 contiguous columns
    bool colok = ((float)(c4 + 3) > gx - POS_MARGIN * gw - 1.0f) &&
                 ((float)c4       < gx + POS_MARGIN * gw);
    float gylo = gy - POS_MARGIN * gh - 1.0f, gyhi = gy + POS_MARGIN * gh;
    int gxi = (int)gx, gyi = (int)gy;
    int colk = gxi - c4;
    bool colown = (unsigned)colk < 4u;

    const float* pw_plane = slabp + 2 * (size_t)PLANE;
    const float* ph_plane = slabp + 3 * (size_t)PLANE;

    float conf2f = 0.0f;
    float selv = 0.0f;
    int cnt = 0;

    #pragma unroll
    for (int s = 0; s < NSTAGES; s++) {
        mbar_wait(s2u(&mbar[s]), 0);

        int j = j0 + s * ROWS_PER_STAGE + r;
        float fj = (float)j;
        float4 cf4 = *(const float4*)&sbuf[s][r * NW + c4];
        float pc4[4] = {cf4.x, cf4.y, cf4.z, cf4.w};

        // hot: unconditional conf^2 (corrected in the rare path)
        #pragma unroll
        for (int k = 0; k < 4; k++) {
            float rr = sig_fast(pc4[k]);
            conf2f += rr * rr;
        }

        // positional band: only here can iou>0.6 occur -> w/h needed
        bool inband = colok && (fj > gylo) && (fj < gyhi);

        // lazy exclusion ownership (gt cell is always inside the band)
        int kx = -1;
        if (colown && gyi == j) {
            float i0v = fminf(gw, a0w) * fminf(gh, a0h);
            float u0v = ga + 1e-16f + a0w * a0h - i0v;
            float i1v = fminf(gw, a1w) * fminf(gh, a1h);
            float u1v = ga + 1e-16f + a1w * a1h - i1v;
            int best = (i1v * u0v > i0v * u1v) ? 1 : 0;
            if (best == a) kx = colk;
        }

        if (inband | (kx >= 0)) {
            size_t roff = (size_t)j * NW + c4;
            float4 w4 = __ldg((const float4*)(pw_plane + roff));
            float4 h4 = __ldg((const float4*)(ph_plane + roff));
            float pw4[4] = {w4.x, w4.y, w4.z, w4.w};
            float ph4[4] = {h4.x, h4.y, h4.z, h4.w};

            bool pass[4];
            bool anyp = false;
            #pragma unroll
            for (int k = 0; k < 4; k++) {
                pass[k] = fabsf(pw4[k] + ph4[k] - cc) < LN_MARGIN;
                anyp |= pass[k];
            }

            if (anyp | (kx >= 0)) {
                const float* prow = slabp + roff;
                float4 x4 = __ldg((const float4*)(prow));
                float4 y4 = __ldg((const float4*)(prow + (size_t)PLANE));
                float px4[4] = {x4.x, x4.y, x4.z, x4.w};
                float py4[4] = {y4.x, y4.y, y4.z, y4.w};
                float gxm = gx - gw * 0.5f, gxM = gx + gw * 0.5f;
                float gym = gy - gh * 0.5f, gyM = gy + gh * 0.5f;

                #pragma unroll
                for (int k = 0; k < 4; k++) {       // compile-time indices
                    bool is_excl = (k == kx);
                    if (pass[k] | is_excl) {
                        float px = sig_fast(px4[k]) + (float)(c4 + k);
                        float py = sig_fast(py4[k]) + fj;
                        float pw = __expf(pw4[k]) * aw;
                        float ph = __expf(ph4[k]) * ah;
                        float mx = fminf(px - pw * 0.5f, gxm);
                        float Mx = fmaxf(px + pw * 0.5f, gxM);
                        float my = fminf(py - ph * 0.5f, gym);
                        float My = fmaxf(py + ph * 0.5f, gyM);
                        float cw = pw + gw - (Mx - mx);
                        float ch = ph + gh - (My - my);
                        float carea = cw * ch;
                        float uarea = pw * ph + ga - carea;
                        bool noobj = (cw <= 0.0f) || (ch <= 0.0f) ||
                                     (carea <= THRESH * uarea);
                        if ((pass[k] && !noobj) || is_excl) {
                            float rr = sig_fast(pc4[k]);   // exact cancel
                            conf2f -= rr * rr;
                            cnt--;
                        }
                        if (is_excl) {
                            float tscale = 2.0f - t.z * t.w;
                            float xs = sig_fast(px4[k]);
                            float ys = sig_fast(py4[k]);
                            float cs = sig_fast(pc4[k]);
                            float txv = gx - floorf(gx), tyv = gy - floorf(gy);
                            float twv = __logf(__fdividef(gw, aw) + 1e-16f);
                            float thv = __logf(__fdividef(gh, ah) + 1e-16f);
                            float dx = (xs - txv) * tscale, dy = (ys - tyv) * tscale;
                            float dw = (pw4[k] - twv) * tscale;
                            float dh = (ph4[k] - thv) * tscale;
                            selv += (dx*dx + dy*dy + dw*dw + dh*dh
                                  + OBJ_SCALE * (cs - 1.0f) * (cs - 1.0f))
                                  * (1.0f / (float)NB);
                        }
                    }
                }
            }
        }
    }

    // ---- block reduce (conf2, cnt, selv) ----
    #pragma unroll
    for (int o = 16; o > 0; o >>= 1) {
        conf2f += __shfl_down_sync(0xffffffffu, conf2f, o);
        cnt    += __shfl_down_sync(0xffffffffu, cnt, o);
        selv   += __shfl_down_sync(0xffffffffu, selv, o);
    }
    int lane = tid & 31, wrp = tid >> 5;
    if (lane == 0) { sh_c2[wrp] = (double)conf2f; sh_ct[wrp] = cnt; sh_sv[wrp] = selv; }
    __syncthreads();
    if (wrp == 0) {
        double c2 = (lane < 8) ? sh_c2[lane] : 0.0;
        int    ct = (lane < 8) ? sh_ct[lane] : 0;
        float  sv = (lane < 8) ? sh_sv[lane] : 0.0f;
        #pragma unroll
        for (int o = 4; o > 0; o >>= 1) {
            c2 += __shfl_down_sync(0xffffffffu, c2, o);
            ct += __shfl_down_sync(0xffffffffu, ct, o);
            sv += __shfl_down_sync(0xffffffffu, sv, o);
        }
        if (lane == 0) {
            atomicAdd(&g_conf2, c2);
            if (ct != 0) atomicAdd(&g_cnt, (unsigned long long)(long long)ct);
            if (sv != 0.0f) atomicAdd(&g_sel, sv);
            __threadfence();
            unsigned old = atomicAdd(&g_done, 1u);
            if (old == (unsigned)(NBLOCKS - 1)) {
                __threadfence();
                double n_noobj = (double)(TOTAL_CELLS + (long long)g_cnt);
                res[0] = g_sel + (float)(g_conf2 / n_noobj);
                g_conf2 = 0.0; g_cnt = 0ull; g_sel = 0.0f; g_done = 0u;
            }
        }
    }
}

extern "C" void kernel_launch(void* const* d_in, const int* in_sizes, int n_in,
                              void* d_out, int out_size) {
    const float* out = (const float*)d_in[0];   // (128, 10, 128, 128)
    const float* tgt = (const float*)d_in[1];   // (128, 4)
    const float* anc = (const float*)d_in[2];   // (2, 2)
    float* res = (float*)d_out;

    k_fused<<<NBLOCKS, 256>>>(out, tgt, anc, res);
}

// round 15
// speedup vs baseline: 1.0133x; 1.0133x over previous
#include <cuda_runtime.h>
#include <math.h>
#include <float.h>

constexpr int NB = 128, NA = 2, NH = 128, NW = 128;
constexpr int PLANE = NH * NW;
constexpr float THRESH = 0.6f;
constexpr float OBJ_SCALE = 5.0f;
constexpr float LN_MARGIN = 0.55961579f;   // ln(1.75) > ln(5/3)+fastlog-err margin
constexpr float POS_MARGIN = 1.30f;        // > 1.2889 exact positional bound
constexpr int NBLOCKS = 2048;              // 524288 threads * 8 cells
constexpr long long TOTAL_CELLS = (long long)NB * NA * NH * NW;  // 4194304

// Accumulators (zero at module load; reset by last block each run)
__device__ double g_conf2 = 0.0;
__device__ unsigned long long g_cnt = 0ull;   // corrections only (negative)
__device__ float  g_sel = 0.0f;
__device__ unsigned g_done = 0u;

__device__ __forceinline__ float sig_fast(float x) {
    return __fdividef(1.0f, 1.0f + __expf(-x));
}

__global__ void __launch_bounds__(256) k_fused(const float* __restrict__ out,
                                               const float* __restrict__ tgt,
                                               const float* __restrict__ anc,
                                               float* __restrict__ res) {
    int gtid = blockIdx.x * 256 + threadIdx.x;
    int i8 = (gtid & 15) * 8;         // 8 contiguous columns
    int r  = gtid >> 4;
    int j  = r & 127; r >>= 7;        // row
    int a  = r & 1;                   // anchor (block-uniform)
    int b  = r >> 1;                  // batch  (block-uniform)

    // ---- constants FIRST: band membership is data-independent ----
    float4 t = __ldg((const float4*)(tgt + b * 4));     // warp-broadcast
    float gx = t.x * (float)NW, gy = t.y * (float)NH;
    float gw = t.z * (float)NW, gh = t.w * (float)NH;

    float fj = (float)j;
    bool rowok = (fj > gy - POS_MARGIN * gh - 1.0f) && (fj < gy + POS_MARGIN * gh);
    bool colok = ((float)(i8 + 7) > gx - POS_MARGIN * gw - 1.0f) &&
                 ((float)i8       < gx + POS_MARGIN * gw);
    bool inband = rowok & colok;

    // ---- loads: conf always; w/h only in band (front-batched, no sync) ----
    const float* pbase = out + ((size_t)(b * 10 + a * 5) * NH + j) * NW + i8;
    float4 c0 = *(const float4*)(pbase + 4 * (size_t)PLANE);
    float4 c1 = *(const float4*)(pbase + 4 * (size_t)PLANE + 4);

    float4 w0, w1, h0, h1;
    if (inband) {
        w0 = *(const float4*)(pbase + 2 * (size_t)PLANE);
        w1 = *(const float4*)(pbase + 2 * (size_t)PLANE + 4);
        h0 = *(const float4*)(pbase + 3 * (size_t)PLANE);
        h1 = *(const float4*)(pbase + 3 * (size_t)PLANE + 4);
    }

    float a0w = __ldg(anc + 0), a0h = __ldg(anc + 1);
    float a1w = __ldg(anc + 2), a1h = __ldg(anc + 3);
    float aw = a ? a1w : a0w;
    float ah = a ? a1h : a0h;
    float ga = gw * gh;

    // lazy exclusion ownership (gt cell is always inside the band)
    int gxi = (int)gx, gyi = (int)gy;
    int colk = gxi - i8;
    int kx = -1;
    if ((unsigned)colk < 8u && gyi == j) {
        float i0v = fminf(gw, a0w) * fminf(gh, a0h);
        float u0v = ga + 1e-16f + a0w * a0h - i0v;
        float i1v = fminf(gw, a1w) * fminf(gh, a1h);
        float u1v = ga + 1e-16f + a1w * a1h - i1v;
        int best = (i1v * u0v > i0v * u1v) ? 1 : 0;
        if (best == a) kx = colk;
    }

    float pc8[8] = {c0.x,c0.y,c0.z,c0.w,c1.x,c1.y,c1.z,c1.w};

    // ---- hot: unconditional conf^2 (corrected in the rare path) ----
    float conf2f = 0.0f;
    #pragma unroll
    for (int k = 0; k < 8; k++) {
        float rr = sig_fast(pc8[k]);
        conf2f += rr * rr;
    }

    // ---- band path (~38% of threads): area screen, then rare exact IoU ----
    float selv = 0.0f;
    int cnt = 0;
    if (inband | (kx >= 0)) {
        float pw8[8] = {w0.x,w0.y,w0.z,w0.w,w1.x,w1.y,w1.z,w1.w};
        float ph8[8] = {h0.x,h0.y,h0.z,h0.w,h1.x,h1.y,h1.z,h1.w};
        float cc = __logf(__fdividef(ga, aw * ah));

        bool pass[8];
        bool anyp = false;
        #pragma unroll
        for (int k = 0; k < 8; k++) {
            pass[k] = fabsf(pw8[k] + ph8[k] - cc) < LN_MARGIN;
            anyp |= pass[k];
        }

        if (anyp | (kx >= 0)) {
            float4 x0 = *(const float4*)(pbase);
            float4 x1 = *(const float4*)(pbase + 4);
            float4 y0 = *(const float4*)(pbase + (size_t)PLANE);
            float4 y1 = *(const float4*)(pbase + (size_t)PLANE + 4);
            float px8[8] = {x0.x,x0.y,x0.z,x0.w,x1.x,x1.y,x1.z,x1.w};
            float py8[8] = {y0.x,y0.y,y0.z,y0.w,y1.x,y1.y,y1.z,y1.w};
            float gxm = gx - gw * 0.5f, gxM = gx + gw * 0.5f;
            float gym = gy - gh * 0.5f, gyM = gy + gh * 0.5f;

            #pragma unroll
            for (int k = 0; k < 8; k++) {        // compile-time indices
                bool is_excl = (k == kx);
                if (pass[k] | is_excl) {
                    float px = sig_fast(px8[k]) + (float)(i8 + k);
                    float py = sig_fast(py8[k]) + fj;
                    float pw = __expf(pw8[k]) * aw;
                    float ph = __expf(ph8[k]) * ah;
                    float mx = fminf(px - pw * 0.5f, gxm);
                    float Mx = fmaxf(px + pw * 0.5f, gxM);
                    float my = fminf(py - ph * 0.5f, gym);
                    float My = fmaxf(py + ph * 0.5f, gyM);
                    float cw = pw + gw - (Mx - mx);
                    float ch = ph + gh - (My - my);
                    float carea = cw * ch;
                    float uarea = pw * ph + ga - carea;
                    bool noobj = (cw <= 0.0f) || (ch <= 0.0f) ||
                                 (carea <= THRESH * uarea);
                    if ((pass[k] && !noobj) || is_excl) {
                        float rr = sig_fast(pc8[k]);   // exact cancel
                        conf2f -= rr * rr;
                        cnt--;
                    }
                    if (is_excl) {
                        float tscale = 2.0f - t.z * t.w;
                        float xs = sig_fast(px8[k]);
                        float ys = sig_fast(py8[k]);
                        float cs = sig_fast(pc8[k]);
                        float txv = gx - floorf(gx), tyv = gy - floorf(gy);
                        float twv = __logf(__fdividef(gw, aw) + 1e-16f);
                        float thv = __logf(__fdividef(gh, ah) + 1e-16f);
                        float dx = (xs - txv) * tscale, dy = (ys - tyv) * tscale;
                        float dw = (pw8[k] - twv) * tscale;
                        float dh = (ph8[k] - thv) * tscale;
                        selv += (dx*dx + dy*dy + dw*dw + dh*dh
                              + OBJ_SCALE * (cs - 1.0f) * (cs - 1.0f))
                              * (1.0f / (float)NB);
                    }
                }
            }
        }
    }

    // ---- block reduce (conf2, cnt, selv) ----
    #pragma unroll
    for (int o = 16; o > 0; o >>= 1) {
        conf2f += __shfl_down_sync(0xffffffffu, conf2f, o);
        cnt    += __shfl_down_sync(0xffffffffu, cnt, o);
        selv   += __shfl_down_sync(0xffffffffu, selv, o);
    }
    __shared__ double sh_c2[8];
    __shared__ int    sh_ct[8];
    __shared__ float  sh_sv[8];
    int lane = threadIdx.x & 31, wrp = threadIdx.x >> 5;
    if (lane == 0) { sh_c2[wrp] = (double)conf2f; sh_ct[wrp] = cnt; sh_sv[wrp] = selv; }
    __syncthreads();
    if (wrp == 0) {
        double c2 = (lane < 8) ? sh_c2[lane] : 0.0;
        int    ct = (lane < 8) ? sh_ct[lane] : 0;
        float  sv = (lane < 8) ? sh_sv[lane] : 0.0f;
        #pragma unroll
        for (int o = 4; o > 0; o >>= 1) {
            c2 += __shfl_down_sync(0xffffffffu, c2, o);
            ct += __shfl_down_sync(0xffffffffu, ct, o);
            sv += __shfl_down_sync(0xffffffffu, sv, o);
        }
        if (lane == 0) {
            atomicAdd(&g_conf2, c2);
            if (ct != 0) atomicAdd(&g_cnt, (unsigned long long)(long long)ct);
            if (sv != 0.0f) atomicAdd(&g_sel, sv);
            __threadfence();
            unsigned old = atomicAdd(&g_done, 1u);
            if (old == (unsigned)(NBLOCKS - 1)) {
                __threadfence();
                double n_noobj = (double)(TOTAL_CELLS + (long long)g_cnt);
                res[0] = g_sel + (float)(g_conf2 / n_noobj);
                g_conf2 = 0.0; g_cnt = 0ull; g_sel = 0.0f; g_done = 0u;
            }
        }
    }
}

extern "C" void kernel_launch(void* const* d_in, const int* in_sizes, int n_in,
                              void* d_out, int out_size) {
    const float* out = (const float*)d_in[0];   // (128, 10, 128, 128)
    const float* tgt = (const float*)d_in[1];   // (128, 4)
    const float* anc = (const float*)d_in[2];   // (2, 2)
    float* res = (float*)d_out;

    k_fused<<<NBLOCKS, 256>>>(out, tgt, anc, res);
}

// round 16
// speedup vs baseline: 1.1359x; 1.1210x over previous
#include <cuda_runtime.h>
#include <math.h>
#include <float.h>

constexpr int NB = 128, NA = 2, NH = 128, NW = 128;
constexpr int PLANE = NH * NW;
constexpr float THRESH = 0.6f;
constexpr float OBJ_SCALE = 5.0f;
constexpr float LN_MARGIN = 0.55961579f;   // ln(1.75) > ln(5/3)+fastlog-err margin
constexpr float POS_MARGIN = 1.30f;        // > 1.2889 exact positional bound
constexpr int NBLOCKS = 2048;              // 524288 threads * 8 cells
constexpr long long TOTAL_CELLS = (long long)NB * NA * NH * NW;  // 4194304

// Accumulators (zero at module load; reset by last block each run)
__device__ double g_conf2 = 0.0;
__device__ unsigned long long g_cnt = 0ull;   // corrections only (negative)
__device__ float  g_sel = 0.0f;
__device__ unsigned g_done = 0u;

__device__ __forceinline__ float sig_fast(float x) {
    return __fdividef(1.0f, 1.0f + __expf(-x));
}

__global__ void __launch_bounds__(256) k_fused(const float* __restrict__ out,
                                               const float* __restrict__ tgt,
                                               const float* __restrict__ anc,
                                               float* __restrict__ res) {
    int gtid = blockIdx.x * 256 + threadIdx.x;
    int i8 = (gtid & 15) * 8;         // 8 contiguous columns
    int r  = gtid >> 4;
    int j  = r & 127; r >>= 7;        // row
    int a  = r & 1;                   // anchor (block-uniform)
    int b  = r >> 1;                  // batch  (block-uniform)

    // ---- conf loads first (independent of everything but indices) ----
    const float* pbase = out + ((size_t)(b * 10 + a * 5) * NH + j) * NW + i8;
    float4 c0 = *(const float4*)(pbase + 4 * (size_t)PLANE);
    float4 c1 = *(const float4*)(pbase + 4 * (size_t)PLANE + 4);

    // ---- band membership from target alone ----
    float4 t = __ldg((const float4*)(tgt + b * 4));     // warp-broadcast
    float gx = t.x * (float)NW, gy = t.y * (float)NH;
    float gw = t.z * (float)NW, gh = t.w * (float)NH;

    float fj = (float)j;
    bool rowok = (fj > gy - POS_MARGIN * gh - 1.0f) && (fj < gy + POS_MARGIN * gh);
    bool colok = ((float)(i8 + 7) > gx - POS_MARGIN * gw - 1.0f) &&
                 ((float)i8       < gx + POS_MARGIN * gw);
    bool inband = rowok & colok;
    int  gyi = (int)gy;
    int  colk = (int)gx - i8;
    bool maybe_own = ((unsigned)colk < 8u) & (gyi == j);   // gt cell in my window?

    // ---- hot: unconditional conf^2 (corrections folded in below) ----
    float pc8[8] = {c0.x,c0.y,c0.z,c0.w,c1.x,c1.y,c1.z,c1.w};
    float conf2f = 0.0f;
    #pragma unroll
    for (int k = 0; k < 8; k++) {
        float rr = sig_fast(pc8[k]);
        conf2f += rr * rr;
    }

    // ---- band path (~38% of threads) ----
    if (inband | maybe_own) {
        float4 w0 = *(const float4*)(pbase + 2 * (size_t)PLANE);
        float4 w1 = *(const float4*)(pbase + 2 * (size_t)PLANE + 4);
        float4 h0 = *(const float4*)(pbase + 3 * (size_t)PLANE);
        float4 h1 = *(const float4*)(pbase + 3 * (size_t)PLANE + 4);
        float pw8[8] = {w0.x,w0.y,w0.z,w0.w,w1.x,w1.y,w1.z,w1.w};
        float ph8[8] = {h0.x,h0.y,h0.z,h0.w,h1.x,h1.y,h1.z,h1.w};

        float a0w = __ldg(anc + 0), a0h = __ldg(anc + 1);
        float a1w = __ldg(anc + 2), a1h = __ldg(anc + 3);
        float aw = a ? a1w : a0w;
        float ah = a ? a1h : a0h;
        float ga = gw * gh;
        float cc = __logf(__fdividef(ga, aw * ah));

        int kx = -1;
        if (maybe_own) {
            float i0v = fminf(gw, a0w) * fminf(gh, a0h);
            float u0v = ga + 1e-16f + a0w * a0h - i0v;
            float i1v = fminf(gw, a1w) * fminf(gh, a1h);
            float u1v = ga + 1e-16f + a1w * a1h - i1v;
            int best = (i1v * u0v > i0v * u1v) ? 1 : 0;
            if (best == a) kx = colk;
        }

        bool pass[8];
        bool anyp = false;
        #pragma unroll
        for (int k = 0; k < 8; k++) {
            pass[k] = inband && (fabsf(pw8[k] + ph8[k] - cc) < LN_MARGIN);
            anyp |= pass[k];
        }

        if (anyp | (kx >= 0)) {
            float4 x0 = *(const float4*)(pbase);
            float4 x1 = *(const float4*)(pbase + 4);
            float4 y0 = *(const float4*)(pbase + (size_t)PLANE);
            float4 y1 = *(const float4*)(pbase + (size_t)PLANE + 4);
            float px8[8] = {x0.x,x0.y,x0.z,x0.w,x1.x,x1.y,x1.z,x1.w};
            float py8[8] = {y0.x,y0.y,y0.z,y0.w,y1.x,y1.y,y1.z,y1.w};
            float gxm = gx - gw * 0.5f, gxM = gx + gw * 0.5f;
            float gym = gy - gh * 0.5f, gyM = gy + gh * 0.5f;

            int cnt = 0;
            #pragma unroll
            for (int k = 0; k < 8; k++) {        // compile-time indices
                bool is_excl = (k == kx);
                if (pass[k] | is_excl) {
                    float px = sig_fast(px8[k]) + (float)(i8 + k);
                    float py = sig_fast(py8[k]) + fj;
                    float pw = __expf(pw8[k]) * aw;
                    float ph = __expf(ph8[k]) * ah;
                    float mx = fminf(px - pw * 0.5f, gxm);
                    float Mx = fmaxf(px + pw * 0.5f, gxM);
                    float my = fminf(py - ph * 0.5f, gym);
                    float My = fmaxf(py + ph * 0.5f, gyM);
                    float cw = pw + gw - (Mx - mx);
                    float ch = ph + gh - (My - my);
                    float carea = cw * ch;
                    float uarea = pw * ph + ga - carea;
                    bool noobj = (cw <= 0.0f) || (ch <= 0.0f) ||
                                 (carea <= THRESH * uarea);
                    if ((pass[k] && !noobj) || is_excl) {
                        float rr = sig_fast(pc8[k]);   // exact cancel
                        conf2f -= rr * rr;
                        cnt--;
                    }
                    if (is_excl) {
                        float tscale = 2.0f - t.z * t.w;
                        float xs = sig_fast(px8[k]);
                        float ys = sig_fast(py8[k]);
                        float cs = sig_fast(pc8[k]);
                        float txv = gx - floorf(gx), tyv = gy - floorf(gy);
                        float twv = __logf(__fdividef(gw, aw) + 1e-16f);
                        float thv = __logf(__fdividef(gh, ah) + 1e-16f);
                        float dx = (xs - txv) * tscale, dy = (ys - tyv) * tscale;
                        float dw = (pw8[k] - twv) * tscale;
                        float dh = (ph8[k] - thv) * tscale;
                        // rare (<=1 thread/batch): direct global atomic
                        atomicAdd(&g_sel, (dx*dx + dy*dy + dw*dw + dh*dh
                              + OBJ_SCALE * (cs - 1.0f) * (cs - 1.0f))
                              * (1.0f / (float)NB));
                    }
                }
            }
            // rare (~few thousand threads total): direct global atomic
            if (cnt != 0)
                atomicAdd(&g_cnt, (unsigned long long)(long long)cnt);
        }
    }

    // ---- single-quantity block reduce ----
    #pragma unroll
    for (int o = 16; o > 0; o >>= 1)
        conf2f += __shfl_down_sync(0xffffffffu, conf2f, o);

    __shared__ float sh_c2[8];
    int lane = threadIdx.x & 31, wrp = threadIdx.x >> 5;
    if (lane == 0) sh_c2[wrp] = conf2f;
    __syncthreads();
    if (wrp == 0) {
        float v = (lane < 8) ? sh_c2[lane] : 0.0f;
        #pragma unroll
        for (int o = 4; o > 0; o >>= 1)
            v += __shfl_down_sync(0xffffffffu, v, o);
        if (lane == 0) {
            atomicAdd(&g_conf2, (double)v);
            __threadfence();
            unsigned old = atomicAdd(&g_done, 1u);
            if (old == (unsigned)(NBLOCKS - 1)) {
                __threadfence();
                double n_noobj = (double)(TOTAL_CELLS + (long long)g_cnt);
                res[0] = g_sel + (float)(g_conf2 / n_noobj);
                g_conf2 = 0.0; g_cnt = 0ull; g_sel = 0.0f; g_done = 0u;
            }
        }
    }
}

extern "C" void kernel_launch(void* const* d_in, const int* in_sizes, int n_in,
                              void* d_out, int out_size) {
    const float* out = (const float*)d_in[0];   // (128, 10, 128, 128)
    const float* tgt = (const float*)d_in[1];   // (128, 4)
    const float* anc = (const float*)d_in[2];   // (2, 2)
    float* res = (float*)d_out;

    k_fused<<<NBLOCKS, 256>>>(out, tgt, anc, res);
}